// round 4
// baseline (speedup 1.0000x reference)
#include <cuda_runtime.h>
#include <cuda_fp16.h>

// ---------------- problem constants ----------------
#define NMAX 50000
#define EMAX 800000
#define MKER 27            // 3^3 spline kernels
#define C    64            // hidden channels
#define ASTR (MKER * C)    // 1728 halves per node (acc row)
#define SSTR 108           // 27 * 4 (ci0,ci1,ci2,pad) layer-0 agg row
#define WTS  68            // padded smem stride for W tile

// ---------------- static scratch ----------------
__device__ __half g_acc[(size_t)NMAX * ASTR];  // 172.8 MB dst-space aggregate (fp16)
__device__ __half g_hh[NMAX * C];              // hidden state (fp16, 6.4 MB: L2-resident)
__device__ float  g_S[NMAX * SSTR];            // layer-0 input-space agg (21.6 MB)
__device__ float4 g_rec[EMAX];                 // CSR edge records: (src, ea0, ea1, ea2)
__device__ int    g_rowptr[NMAX + 1];
__device__ int    g_cursor[NMAX];
__device__ int    g_deg[NMAX];

// ---------------- helpers ----------------
__device__ __forceinline__ float2 ffma2(float2 a, float2 b, float2 c) {
    float2 d;
    asm("fma.rn.f32x2 %0, %1, %2, %3;"
        : "=l"(*reinterpret_cast<unsigned long long*>(&d))
        : "l"(*reinterpret_cast<unsigned long long*>(&a)),
          "l"(*reinterpret_cast<unsigned long long*>(&b)),
          "l"(*reinterpret_cast<unsigned long long*>(&c)));
    return d;
}

__device__ __forceinline__ void basis8(float e0, float e1, float e2,
                                       float w[8], int kk[8]) {
    float p0 = e0 * 2.0f, p1 = e1 * 2.0f, p2 = e2 * 2.0f;
    float f0 = fminf(fmaxf(floorf(p0), 0.f), 1.f);
    float f1 = fminf(fmaxf(floorf(p1), 0.f), 1.f);
    float f2 = fminf(fmaxf(floorf(p2), 0.f), 1.f);
    float u0 = p0 - f0, u1 = p1 - f1, u2 = p2 - f2;
    int base = (int)f0 + 3 * (int)f1 + 9 * (int)f2;
#pragma unroll
    for (int b = 0; b < 8; b++) {
        float a0 = (b & 1) ? u0 : 1.f - u0;
        float a1 = (b & 2) ? u1 : 1.f - u1;
        float a2 = (b & 4) ? u2 : 1.f - u2;
        w[b]  = a0 * a1 * a2;
        kk[b] = base + (b & 1) + 3 * ((b >> 1) & 1) + 9 * ((b >> 2) & 1);
    }
}

// 3-tap basis vector per dim: d[j] = linear B-spline value at knot j
__device__ __forceinline__ void basis3(float e, float d[3]) {
    float p = e * 2.0f;
    float f = fminf(fmaxf(floorf(p), 0.f), 1.f);
    float u = p - f;
    bool hi = (f > 0.5f);       // i0 == 1
    d[0] = hi ? 0.f : 1.f - u;
    d[1] = hi ? 1.f - u : u;
    d[2] = hi ? u : 0.f;
}

// ---------------- CSR build ----------------
__global__ void zeroAll_kernel(int N) {
    int i = blockIdx.x * blockDim.x + threadIdx.x;
    if (i < N * SSTR) g_S[i] = 0.f;
    if (i < N)        g_deg[i] = 0;
}
__global__ void hist_kernel(const int* __restrict__ dst, int E) {
    int i = blockIdx.x * blockDim.x + threadIdx.x;
    if (i < E) atomicAdd(&g_deg[dst[i]], 1);
}
// single-block exclusive scan of g_deg -> g_rowptr (and g_cursor copy)
__global__ void scan_kernel(int N) {
    __shared__ int ssum[1024];
    int tid = threadIdx.x;
    int chunk = (N + 1023) / 1024;
    int beg = tid * chunk;
    int end = min(beg + chunk, N);
    int s = 0;
    for (int i = beg; i < end; i++) s += g_deg[i];
    ssum[tid] = s;
    __syncthreads();
    for (int off = 1; off < 1024; off <<= 1) {
        int v = 0;
        if (tid >= off) v = ssum[tid - off];
        __syncthreads();
        if (tid >= off) ssum[tid] += v;
        __syncthreads();
    }
    int run = (tid == 0) ? 0 : ssum[tid - 1];
    for (int i = beg; i < end; i++) {
        g_rowptr[i] = run;
        g_cursor[i] = run;
        run += g_deg[i];
    }
    if (tid == 1023) g_rowptr[N] = ssum[1023];
}

// edge pass: write CSR record + layer-0 input-space scatter (float4 RED)
__global__ void build_kernel(const int* __restrict__ src,
                             const int* __restrict__ dst,
                             const float* __restrict__ ea,
                             const float* __restrict__ x, int E) {
    int e = blockIdx.x * blockDim.x + threadIdx.x;
    if (e >= E) return;
    int s = src[e], d = dst[e];
    float e0 = ea[3 * e], e1 = ea[3 * e + 1], e2 = ea[3 * e + 2];

    int pos = atomicAdd(&g_cursor[d], 1);
    g_rec[pos] = make_float4(__int_as_float(s), e0, e1, e2);

    float w[8]; int kk[8];
    basis8(e0, e1, e2, w, kk);
    float x0 = __ldg(x + 3 * s), x1 = __ldg(x + 3 * s + 1), x2 = __ldg(x + 3 * s + 2);
    float4* Sb = (float4*)(g_S + (size_t)d * SSTR);
#pragma unroll
    for (int c = 0; c < 8; c++)
        atomicAdd(Sb + kk[c], make_float4(w[c] * x0, w[c] * x1, w[c] * x2, 0.f));
}

// ---------------- layer 0 finalize: h = relu(S@W0/deg + x@root0 + b0) --------
__global__ void __launch_bounds__(256)
l0_kernel(const float* __restrict__ x, const float* __restrict__ W0,
          const float* __restrict__ root0, const float* __restrict__ b0, int N) {
    int n    = (blockIdx.x * blockDim.x + threadIdx.x) >> 5;
    int lane = threadIdx.x & 31;
    if (n >= N) return;
    const float* Sr = g_S + (size_t)n * SSTR;
    float sA = Sr[lane];
    float sB = Sr[32 + lane];
    float sC = Sr[64 + lane];
    float sD = (lane < 12) ? Sr[96 + lane] : 0.f;

    float2 acc = make_float2(0.f, 0.f);
#pragma unroll
    for (int m = 0; m < MKER; m++) {
#pragma unroll
        for (int ci = 0; ci < 3; ci++) {
            int s  = m * 4 + ci;
            int r  = s >> 5, sl = s & 31;
            float v = (r == 0) ? __shfl_sync(0xffffffffu, sA, sl)
                    : (r == 1) ? __shfl_sync(0xffffffffu, sB, sl)
                    : (r == 2) ? __shfl_sync(0xffffffffu, sC, sl)
                               : __shfl_sync(0xffffffffu, sD, sl);
            float2 wv = __ldg((const float2*)(W0 + (m * 3 + ci) * C) + lane);
            acc.x += v * wv.x;
            acc.y += v * wv.y;
        }
    }
    int   dg  = g_rowptr[n + 1] - g_rowptr[n];
    float inv = 1.f / (float)(dg > 0 ? dg : 1);
    float xv  = (lane < 3) ? __ldg(x + 3 * n + lane) : 0.f;
    float x0  = __shfl_sync(0xffffffffu, xv, 0);
    float x1  = __shfl_sync(0xffffffffu, xv, 1);
    float x2  = __shfl_sync(0xffffffffu, xv, 2);
    float2 r0 = __ldg((const float2*)(root0)         + lane);
    float2 r1 = __ldg((const float2*)(root0 + C)     + lane);
    float2 r2 = __ldg((const float2*)(root0 + 2 * C) + lane);
    float2 bb = __ldg((const float2*)(b0)            + lane);
    float v0  = fmaxf(acc.x * inv + x0 * r0.x + x1 * r1.x + x2 * r2.x + bb.x, 0.f);
    float v1  = fmaxf(acc.y * inv + x0 * r0.y + x1 * r1.y + x2 * r2.y + bb.y, 0.f);
    ((__half2*)g_hh)[(size_t)n * 32 + lane] = __floats2half2_rn(v0, v1);
}

// ---------------- edge aggregation (layers 1,2): warp per dst node -----------
// acc[n, m, ci] = sum_e w_m(e) * h[src_e, ci]   (registers; no atomics)
__global__ void __launch_bounds__(256)
edge_acc_kernel(int N) {
    int n    = (blockIdx.x * blockDim.x + threadIdx.x) >> 5;
    int lane = threadIdx.x & 31;
    if (n >= N) return;
    int beg = g_rowptr[n], end = g_rowptr[n + 1];

    float2 acc[MKER];
#pragma unroll
    for (int m = 0; m < MKER; m++) acc[m] = make_float2(0.f, 0.f);

    float4  r  = make_float4(0.f, 0.f, 0.f, 0.f);
    __half2 hv = __half2half2(__float2half(0.f));
    if (beg < end) {
        r  = __ldg(&g_rec[beg]);
        hv = __ldg((const __half2*)(g_hh + (size_t)__float_as_int(r.x) * C) + lane);
    }
    for (int e = beg; e < end; e++) {
        float4  cr = r;
        __half2 ch = hv;
        if (e + 1 < end) {                        // software pipeline next edge
            r  = __ldg(&g_rec[e + 1]);
            hv = __ldg((const __half2*)(g_hh + (size_t)__float_as_int(r.x) * C) + lane);
        }
        float2 v = __half22float2(ch);
        float d0[3], d1[3], d2[3];
        basis3(cr.y, d0); basis3(cr.z, d1); basis3(cr.w, d2);
#pragma unroll
        for (int c2 = 0; c2 < 3; c2++) {
            float2 v2 = make_float2(d2[c2] * v.x, d2[c2] * v.y);
#pragma unroll
            for (int c1 = 0; c1 < 3; c1++) {
                float2 v1 = make_float2(d1[c1] * v2.x, d1[c1] * v2.y);
#pragma unroll
                for (int c0 = 0; c0 < 3; c0++) {
                    int m = c0 + 3 * c1 + 9 * c2;
                    acc[m].x += d0[c0] * v1.x;
                    acc[m].y += d0[c0] * v1.y;
                }
            }
        }
    }
    __half2* ap = (__half2*)(g_acc + (size_t)n * ASTR);
#pragma unroll
    for (int m = 0; m < MKER; m++)
        ap[m * 32 + lane] = __floats2half2_rn(acc[m].x, acc[m].y);
}

// ---------------- fused GEMM + finalize (layers 1,2) -------------------------
// out[n,co] = relu( (sum_m acc[n,m,:] @ W[m]) / deg + h[n] @ Wr + b )
// 64-node tile per block, loop over 28 "m" (27 spline + root), W staged in
// smem (transposed), acc tile staged fp16->fp32; register-prefetch pipeline.
__global__ void __launch_bounds__(256)
gemm_finalize_kernel(const float* __restrict__ W, const float* __restrict__ Wr,
                     const float* __restrict__ bias, float* __restrict__ out32,
                     int N, int writeFloat) {
    __shared__ float Wt[C * WTS];    // [co][ci] padded
    __shared__ float av[64 * C];     // [node][ci] fp32
    int n0  = blockIdx.x * 64;
    int tid = threadIdx.x;

    int sj = tid >> 2;               // staging node 0..63
    int sg = tid & 3;                // staging 16-ch group
    int wb = tid * 16;               // staging W chunk

    float wreg[16];
    uint4 areg0, areg1;

    auto loadStage = [&](int m) {
        const float* Wm = (m < MKER) ? (W + (size_t)m * C * C) : Wr;
#pragma unroll
        for (int k = 0; k < 16; k++) wreg[k] = __ldg(Wm + wb + k);
        int n = n0 + sj;
        if (n < N) {
            const __half* srcp = (m < MKER)
                ? (g_acc + (size_t)n * ASTR + m * C + sg * 16)
                : (g_hh  + (size_t)n * C + sg * 16);
            areg0 = __ldg((const uint4*)srcp);
            areg1 = __ldg((const uint4*)srcp + 1);
        } else {
            areg0 = make_uint4(0, 0, 0, 0);
            areg1 = make_uint4(0, 0, 0, 0);
        }
    };
    auto storeStage = [&]() {
#pragma unroll
        for (int k = 0; k < 16; k++) {
            int idx = wb + k;                       // ci*64 + co
            Wt[(idx & 63) * WTS + (idx >> 6)] = wreg[k];
        }
        float* dstp = &av[sj * C + sg * 16];
        unsigned uu[8] = {areg0.x, areg0.y, areg0.z, areg0.w,
                          areg1.x, areg1.y, areg1.z, areg1.w};
#pragma unroll
        for (int k = 0; k < 8; k++) {
            float2 f = __half22float2(*(__half2*)&uu[k]);
            dstp[2 * k]     = f.x;
            dstp[2 * k + 1] = f.y;
        }
    };

    loadStage(0);
    storeStage();
    __syncthreads();

    int co0 = (tid & 31) * 2;
    int nb  = (tid >> 5) * 8;
    float2 accA[8], accB[8];
#pragma unroll
    for (int j = 0; j < 8; j++) {
        accA[j] = make_float2(0.f, 0.f);
        accB[j] = make_float2(0.f, 0.f);
    }

    for (int m = 0; m < MKER + 1; m++) {
        if (m + 1 < MKER + 1) loadStage(m + 1);    // prefetch into regs
#pragma unroll
        for (int ci = 0; ci < C; ci += 4) {
            float4 wa = *(const float4*)&Wt[co0 * WTS + ci];
            float4 wbv = *(const float4*)&Wt[(co0 + 1) * WTS + ci];
            float2 wa01 = make_float2(wa.x, wa.y), wa23 = make_float2(wa.z, wa.w);
            float2 wb01 = make_float2(wbv.x, wbv.y), wb23 = make_float2(wbv.z, wbv.w);
#pragma unroll
            for (int j = 0; j < 8; j++) {
                float4 hv = *(const float4*)&av[(nb + j) * C + ci];  // broadcast
                float2 h01 = make_float2(hv.x, hv.y), h23 = make_float2(hv.z, hv.w);
                accA[j] = ffma2(h01, wa01, accA[j]);
                accA[j] = ffma2(h23, wa23, accA[j]);
                accB[j] = ffma2(h01, wb01, accB[j]);
                accB[j] = ffma2(h23, wb23, accB[j]);
            }
        }
        if (m == MKER - 1) {     // scale spline part by 1/deg before root row
#pragma unroll
            for (int j = 0; j < 8; j++) {
                int n = n0 + nb + j;
                int dg = (n < N) ? (g_rowptr[n + 1] - g_rowptr[n]) : 1;
                float inv = 1.f / (float)(dg > 0 ? dg : 1);
                accA[j].x *= inv; accA[j].y *= inv;
                accB[j].x *= inv; accB[j].y *= inv;
            }
        }
        __syncthreads();
        if (m + 1 < MKER + 1) {
            storeStage();
            __syncthreads();
        }
    }

    float bv0 = __ldg(bias + co0), bv1 = __ldg(bias + co0 + 1);
#pragma unroll
    for (int j = 0; j < 8; j++) {
        int n = n0 + nb + j;
        if (n >= N) break;
        float v0 = fmaxf(accA[j].x + accA[j].y + bv0, 0.f);
        float v1 = fmaxf(accB[j].x + accB[j].y + bv1, 0.f);
        if (writeFloat) {
            *(float2*)(out32 + (size_t)n * C + co0) = make_float2(v0, v1);
        } else {
            ((__half2*)g_hh)[(size_t)n * 32 + (co0 >> 1)] = __floats2half2_rn(v0, v1);
        }
    }
}

// ---------------- launch ----------------
extern "C" void kernel_launch(void* const* d_in, const int* in_sizes, int n_in,
                              void* d_out, int out_size) {
    const float* x     = (const float*)d_in[0];
    const int*   ei    = (const int*)d_in[1];
    const float* ea    = (const float*)d_in[2];
    const float* W0    = (const float*)d_in[3];
    const float* root0 = (const float*)d_in[4];
    const float* b0    = (const float*)d_in[5];
    const float* W1    = (const float*)d_in[6];
    const float* root1 = (const float*)d_in[7];
    const float* b1    = (const float*)d_in[8];
    const float* W2    = (const float*)d_in[9];
    const float* root2 = (const float*)d_in[10];
    const float* b2    = (const float*)d_in[11];
    float* out = (float*)d_out;

    int N = in_sizes[0] / 3;
    int E = in_sizes[1] / 2;
    const int* src = ei;
    const int* dst = ei + E;

    int nodeBlocks = (N * 32 + 255) / 256;
    int gemmBlocks = (N + 63) / 64;

    // ---- CSR + layer-0 scatter ----
    zeroAll_kernel<<<(N * SSTR + 255) / 256, 256>>>(N);
    hist_kernel<<<(E + 255) / 256, 256>>>(dst, E);
    scan_kernel<<<1, 1024>>>(N);
    build_kernel<<<(E + 255) / 256, 256>>>(src, dst, ea, x, E);

    // ---- layer 0 ----
    l0_kernel<<<nodeBlocks, 256>>>(x, W0, root0, b0, N);

    // ---- layer 1 ----
    edge_acc_kernel<<<nodeBlocks, 256>>>(N);
    gemm_finalize_kernel<<<gemmBlocks, 256>>>(W1, root1, b1, nullptr, N, 0);

    // ---- layer 2 ----
    edge_acc_kernel<<<nodeBlocks, 256>>>(N);
    gemm_finalize_kernel<<<gemmBlocks, 256>>>(W2, root2, b2, out, N, 1);
}

// round 5
// speedup vs baseline: 1.1532x; 1.1532x over previous
#include <cuda_runtime.h>
#include <cuda_fp16.h>

// ---------------- problem constants ----------------
#define NMAX 50000
#define EMAX 800000
#define MKER 27            // 3^3 spline kernels
#define C    64            // hidden channels
#define YSTR (MKER * C)    // 1728 halves per node
#define SSTR 108           // 27 * 4 (ci0,ci1,ci2,pad) layer-0 agg row

// ---------------- static scratch ----------------
__device__ __half g_y[(size_t)NMAX * YSTR];   // 172.8 MB transformed features (fp16)
__device__ float  g_root[NMAX * C];           // fp32 root-weight term h @ Wr
__device__ float  g_h[NMAX * C];              // hidden state (fp32)
__device__ float  g_S[NMAX * SSTR];           // layer-0 input-space agg (21.6 MB)
__device__ float4 g_rec[EMAX];                // CSR edge records: (src, ea0, ea1, ea2)
__device__ int    g_rowptr[NMAX + 1];
__device__ int    g_cursor[NMAX];
__device__ int    g_deg[NMAX];

// ---------------- helpers ----------------
__device__ __forceinline__ float2 ffma2(float2 a, float2 b, float2 c) {
    float2 d;
    asm("fma.rn.f32x2 %0, %1, %2, %3;"
        : "=l"(*reinterpret_cast<unsigned long long*>(&d))
        : "l"(*reinterpret_cast<unsigned long long*>(&a)),
          "l"(*reinterpret_cast<unsigned long long*>(&b)),
          "l"(*reinterpret_cast<unsigned long long*>(&c)));
    return d;
}

__device__ __forceinline__ void basis8(float e0, float e1, float e2,
                                       float w[8], int kk[8]) {
    float p0 = e0 * 2.0f, p1 = e1 * 2.0f, p2 = e2 * 2.0f;
    float f0 = fminf(fmaxf(floorf(p0), 0.f), 1.f);
    float f1 = fminf(fmaxf(floorf(p1), 0.f), 1.f);
    float f2 = fminf(fmaxf(floorf(p2), 0.f), 1.f);
    float u0 = p0 - f0, u1 = p1 - f1, u2 = p2 - f2;
    int base = (int)f0 + 3 * (int)f1 + 9 * (int)f2;
#pragma unroll
    for (int b = 0; b < 8; b++) {
        float a0 = (b & 1) ? u0 : 1.f - u0;
        float a1 = (b & 2) ? u1 : 1.f - u1;
        float a2 = (b & 4) ? u2 : 1.f - u2;
        w[b]  = a0 * a1 * a2;
        kk[b] = base + (b & 1) + 3 * ((b >> 1) & 1) + 9 * ((b >> 2) & 1);
    }
}

// ---------------- CSR build ----------------
__global__ void zeroAll_kernel(int N) {
    int i = blockIdx.x * blockDim.x + threadIdx.x;
    if (i < N * SSTR) g_S[i] = 0.f;
    if (i < N)        g_deg[i] = 0;
}
__global__ void hist_kernel(const int* __restrict__ dst, int E) {
    int i = blockIdx.x * blockDim.x + threadIdx.x;
    if (i < E) atomicAdd(&g_deg[dst[i]], 1);
}
// single-block exclusive scan of g_deg -> g_rowptr (and g_cursor copy)
__global__ void scan_kernel(int N) {
    __shared__ int ssum[1024];
    int tid = threadIdx.x;
    int chunk = (N + 1023) / 1024;
    int beg = tid * chunk;
    int end = min(beg + chunk, N);
    int s = 0;
    for (int i = beg; i < end; i++) s += g_deg[i];
    ssum[tid] = s;
    __syncthreads();
    for (int off = 1; off < 1024; off <<= 1) {
        int v = 0;
        if (tid >= off) v = ssum[tid - off];
        __syncthreads();
        if (tid >= off) ssum[tid] += v;
        __syncthreads();
    }
    int run = (tid == 0) ? 0 : ssum[tid - 1];
    for (int i = beg; i < end; i++) {
        g_rowptr[i] = run;
        g_cursor[i] = run;
        run += g_deg[i];
    }
    if (tid == 1023) g_rowptr[N] = ssum[1023];
}

// edge pass: write CSR record + layer-0 input-space scatter (float4 RED)
__global__ void build_kernel(const int* __restrict__ src,
                             const int* __restrict__ dst,
                             const float* __restrict__ ea,
                             const float* __restrict__ x, int E) {
    int e = blockIdx.x * blockDim.x + threadIdx.x;
    if (e >= E) return;
    int s = src[e], d = dst[e];
    float e0 = ea[3 * e], e1 = ea[3 * e + 1], e2 = ea[3 * e + 2];

    int pos = atomicAdd(&g_cursor[d], 1);
    g_rec[pos] = make_float4(__int_as_float(s), e0, e1, e2);

    float w[8]; int kk[8];
    basis8(e0, e1, e2, w, kk);
    float x0 = __ldg(x + 3 * s), x1 = __ldg(x + 3 * s + 1), x2 = __ldg(x + 3 * s + 2);
    float4* Sb = (float4*)(g_S + (size_t)d * SSTR);
#pragma unroll
    for (int c = 0; c < 8; c++)
        atomicAdd(Sb + kk[c], make_float4(w[c] * x0, w[c] * x1, w[c] * x2, 0.f));
}

// ---------------- layer 0 finalize: h = relu(S@W0/deg + x@root0 + b0) --------
__global__ void __launch_bounds__(256)
l0_kernel(const float* __restrict__ x, const float* __restrict__ W0,
          const float* __restrict__ root0, const float* __restrict__ b0, int N) {
    int n    = (blockIdx.x * blockDim.x + threadIdx.x) >> 5;
    int lane = threadIdx.x & 31;
    if (n >= N) return;
    const float* Sr = g_S + (size_t)n * SSTR;
    float sA = Sr[lane];
    float sB = Sr[32 + lane];
    float sC = Sr[64 + lane];
    float sD = (lane < 12) ? Sr[96 + lane] : 0.f;

    float2 acc = make_float2(0.f, 0.f);
#pragma unroll
    for (int m = 0; m < MKER; m++) {
#pragma unroll
        for (int ci = 0; ci < 3; ci++) {
            int s  = m * 4 + ci;
            int r  = s >> 5, sl = s & 31;
            float v = (r == 0) ? __shfl_sync(0xffffffffu, sA, sl)
                    : (r == 1) ? __shfl_sync(0xffffffffu, sB, sl)
                    : (r == 2) ? __shfl_sync(0xffffffffu, sC, sl)
                               : __shfl_sync(0xffffffffu, sD, sl);
            float2 wv = __ldg((const float2*)(W0 + (m * 3 + ci) * C) + lane);
            acc.x += v * wv.x;
            acc.y += v * wv.y;
        }
    }
    int   dg  = g_rowptr[n + 1] - g_rowptr[n];
    float inv = 1.f / (float)(dg > 0 ? dg : 1);
    float xv  = (lane < 3) ? __ldg(x + 3 * n + lane) : 0.f;
    float x0  = __shfl_sync(0xffffffffu, xv, 0);
    float x1  = __shfl_sync(0xffffffffu, xv, 1);
    float x2  = __shfl_sync(0xffffffffu, xv, 2);
    float2 r0 = __ldg((const float2*)(root0)         + lane);
    float2 r1 = __ldg((const float2*)(root0 + C)     + lane);
    float2 r2 = __ldg((const float2*)(root0 + 2 * C) + lane);
    float2 bb = __ldg((const float2*)(b0)            + lane);
    float2 res;
    res.x = fmaxf(acc.x * inv + x0 * r0.x + x1 * r1.x + x2 * r2.x + bb.x, 0.f);
    res.y = fmaxf(acc.y * inv + x0 * r0.y + x1 * r1.y + x2 * r2.y + bb.y, 0.f);
    ((float2*)g_h)[(size_t)n * 32 + lane] = res;
}

// ---------------- transform: y[n, m, co] = sum_ci h[n,ci] * W[m,ci,co] --------
// block = 256 threads, 64 nodes/block, grid.y = 28 (27 spline m + root row).
// Thread owns 2 adjacent co and 8 nodes; FFMA2-floor bound.
#define T_NODES 64
#define WT_STR  68
__global__ void __launch_bounds__(256)
transform_kernel(const float* __restrict__ h, const float* __restrict__ W,
                 const float* __restrict__ Wr, int N) {
    __shared__ float Wt[C * WT_STR];   // [co][ci], padded stride 68
    __shared__ float hs[T_NODES * C];  // [n][ci]
    int m   = blockIdx.y;
    int n0  = blockIdx.x * T_NODES;
    int tid = threadIdx.x;

    const float* Wm = (m < MKER) ? (W + m * C * C) : Wr;
    for (int i = tid; i < C * C; i += 256) {
        int ci = i >> 6, co = i & 63;
        Wt[co * WT_STR + ci] = Wm[i];
    }
    for (int i = tid; i < T_NODES * C; i += 256) {
        int n = n0 + (i >> 6);
        hs[i] = (n < N) ? h[(size_t)n * C + (i & 63)] : 0.f;
    }
    __syncthreads();

    int co0 = (tid & 31) * 2;
    int nb  = (tid >> 5) * 8;

    float2 acc[8][2];
#pragma unroll
    for (int j = 0; j < 8; j++) {
        acc[j][0] = make_float2(0.f, 0.f);
        acc[j][1] = make_float2(0.f, 0.f);
    }

#pragma unroll
    for (int ci = 0; ci < C; ci += 4) {
        float4 wa = *(const float4*)&Wt[co0 * WT_STR + ci];
        float4 wb = *(const float4*)&Wt[(co0 + 1) * WT_STR + ci];
        float2 wa01 = make_float2(wa.x, wa.y), wa23 = make_float2(wa.z, wa.w);
        float2 wb01 = make_float2(wb.x, wb.y), wb23 = make_float2(wb.z, wb.w);
#pragma unroll
        for (int j = 0; j < 8; j++) {
            float4 hv = *(const float4*)&hs[(nb + j) * C + ci];  // warp-broadcast
            float2 h01 = make_float2(hv.x, hv.y), h23 = make_float2(hv.z, hv.w);
            acc[j][0] = ffma2(h01, wa01, acc[j][0]);
            acc[j][0] = ffma2(h23, wa23, acc[j][0]);
            acc[j][1] = ffma2(h01, wb01, acc[j][1]);
            acc[j][1] = ffma2(h23, wb23, acc[j][1]);
        }
    }

#pragma unroll
    for (int j = 0; j < 8; j++) {
        int n = n0 + nb + j;
        if (n >= N) break;
        float v0 = acc[j][0].x + acc[j][0].y;
        float v1 = acc[j][1].x + acc[j][1].y;
        if (m < MKER) {
            __half2* yp = (__half2*)(g_y + (size_t)n * YSTR + m * C + co0);
            *yp = __floats2half2_rn(v0, v1);
        } else {
            *(float2*)(g_root + (size_t)n * C + co0) = make_float2(v0, v1);
        }
    }
}

// ---------------- node kernel (layers 1,2): warp per dst node ----------------
// CSR records staged via one coalesced float4 load per 32 edges (lane i takes
// rec[base+i] -> smem); edge loop then has no loop-carried memory dependence,
// so the 8 y-row gathers of consecutive edges overlap (high MLP).
__global__ void __launch_bounds__(256)
node_kernel(const float* __restrict__ bias, float* __restrict__ h_out, int N) {
    __shared__ float4 recs[8][32];
    int wid  = threadIdx.x >> 5;
    int lane = threadIdx.x & 31;
    int n    = (blockIdx.x * blockDim.x + threadIdx.x) >> 5;
    if (n >= N) return;
    int beg = g_rowptr[n], end = g_rowptr[n + 1];

    float2 acc = make_float2(0.f, 0.f);
    for (int base = beg; base < end; base += 32) {
        int cnt = min(32, end - base);
        __syncwarp();
        if (lane < cnt) recs[wid][lane] = __ldg(&g_rec[base + lane]);
        __syncwarp();
#pragma unroll 4
        for (int e = 0; e < cnt; e++) {
            float4 r = recs[wid][e];                 // LDS broadcast
            int s = __float_as_int(r.x);
            float w[8]; int kk[8];
            basis8(r.y, r.z, r.w, w, kk);
            const __half* yb = g_y + (size_t)s * YSTR;
#pragma unroll
            for (int c = 0; c < 8; c++) {
                __half2 hv = __ldg((const __half2*)(yb + kk[c] * C) + lane);
                float2 v = __half22float2(hv);
                acc.x += w[c] * v.x;
                acc.y += w[c] * v.y;
            }
        }
    }
    int   dg  = end - beg;
    float inv = 1.f / (float)(dg > 0 ? dg : 1);
    float2 rt = __ldg((const float2*)(g_root + (size_t)n * C) + lane);
    float2 bb = __ldg((const float2*)bias + lane);
    float2 res;
    res.x = fmaxf(acc.x * inv + rt.x + bb.x, 0.f);
    res.y = fmaxf(acc.y * inv + rt.y + bb.y, 0.f);
    ((float2*)h_out)[(size_t)n * 32 + lane] = res;
}

// ---------------- launch ----------------
extern "C" void kernel_launch(void* const* d_in, const int* in_sizes, int n_in,
                              void* d_out, int out_size) {
    const float* x     = (const float*)d_in[0];
    const int*   ei    = (const int*)d_in[1];
    const float* ea    = (const float*)d_in[2];
    const float* W0    = (const float*)d_in[3];
    const float* root0 = (const float*)d_in[4];
    const float* b0    = (const float*)d_in[5];
    const float* W1    = (const float*)d_in[6];
    const float* root1 = (const float*)d_in[7];
    const float* b1    = (const float*)d_in[8];
    const float* W2    = (const float*)d_in[9];
    const float* root2 = (const float*)d_in[10];
    const float* b2    = (const float*)d_in[11];
    float* out = (float*)d_out;

    int N = in_sizes[0] / 3;
    int E = in_sizes[1] / 2;
    const int* src = ei;
    const int* dst = ei + E;

    float* hP;
    cudaGetSymbolAddress((void**)&hP, g_h);

    int nodeBlocks = (N * 32 + 255) / 256;
    dim3 tGrid((N + T_NODES - 1) / T_NODES, MKER + 1);

    // ---- CSR + layer-0 scatter ----
    zeroAll_kernel<<<(N * SSTR + 255) / 256, 256>>>(N);
    hist_kernel<<<(E + 255) / 256, 256>>>(dst, E);
    scan_kernel<<<1, 1024>>>(N);
    build_kernel<<<(E + 255) / 256, 256>>>(src, dst, ea, x, E);

    // ---- layer 0 ----
    l0_kernel<<<nodeBlocks, 256>>>(x, W0, root0, b0, N);

    // ---- layer 1 ----
    transform_kernel<<<tGrid, 256>>>(hP, W1, root1, N);
    node_kernel<<<nodeBlocks, 256>>>(b1, hP, N);

    // ---- layer 2 ----
    transform_kernel<<<tGrid, 256>>>(hP, W2, root2, N);
    node_kernel<<<nodeBlocks, 256>>>(b2, out, N);
}